// round 13
// baseline (speedup 1.0000x reference)
#include <cuda_runtime.h>
#include <cuda_bf16.h>
#include <cuda_fp16.h>

// ---------------------------------------------------------------------------
// Simplex4Net: B=32, N=64, D=64
//   kAB: fused projections + six Gram matrices * 0.0625 (grid (6,32))
//   kC:  grid (64,32) x 512 threads, occ-2 (8 warps/SMSP, 1.2% tail).
//        Thread = (k, l-quad), 2 f16x2 streams, 2 units — lean registers so
//        ptxas can software-pipeline the LDS stream. All-f16 inner chain;
//        gate split (closed-form ungated half); fused MLP head.
// ---------------------------------------------------------------------------

#define BSZ 32
#define NP  64
#define DD  64

__device__ float g_E[6][BSZ][NP * NP];   // 0:(i,j) 1:(i,k) 2:(i,l) 3:(j,k) 4:(j,l) 5:(l,k)^T
__device__ float g_anchor[BSZ * NP];
__device__ unsigned g_done;

typedef unsigned long long ull;

__device__ __forceinline__ ull pk2(float lo, float hi) {
    ull r; asm("mov.b64 %0, {%1, %2};" : "=l"(r) : "f"(lo), "f"(hi)); return r;
}
__device__ __forceinline__ void upk2(ull v, float& lo, float& hi) {
    asm("mov.b64 {%0, %1}, %2;" : "=f"(lo), "=f"(hi) : "l"(v));
}
__device__ __forceinline__ ull fma2(ull a, ull b, ull c) {
    ull r; asm("fma.rn.f32x2 %0, %1, %2, %3;" : "=l"(r) : "l"(a), "l"(b), "l"(c)); return r;
}
__device__ __forceinline__ __half2 tanh2h(__half2 x) {
    unsigned xu = *reinterpret_cast<unsigned*>(&x);
    unsigned yu;
    asm("tanh.approx.f16x2 %0, %1;" : "=r"(yu) : "r"(xu));
    return *reinterpret_cast<__half2*>(&yu);
}
__device__ __forceinline__ __half2 u2h(unsigned u) {
    return *reinterpret_cast<__half2*>(&u);
}

// ---------------------------------------------------------------------------
// kAB: grid (6,32), 256 threads. Builds both projections it needs, writes
// Gram p (pre-scaled 0.0625). p=5 stored transposed [l][k].
// ---------------------------------------------------------------------------
__global__ void kAB(const float* __restrict__ pc,
                    const float* __restrict__ Wq,  const float* __restrict__ bq,
                    const float* __restrict__ Wk1, const float* __restrict__ bk1,
                    const float* __restrict__ Wk2, const float* __restrict__ bk2,
                    const float* __restrict__ Wk3, const float* __restrict__ bk3)
{
    int p = blockIdx.x, b = blockIdx.y, t = threadIdx.x;
    if (p == 0 && b == 0 && t == 0) g_done = 0;

    __shared__ float sp[NP * 3];
    __shared__ float sX[NP][65];
    __shared__ float sY[NP][65];

    const int XI[6] = {0, 0, 0, 1, 1, 3};
    const int YI[6] = {1, 2, 3, 2, 3, 2};
    const float* Ws[4] = {Wq, Wk1, Wk2, Wk3};
    const float* bs[4] = {bq, bk1, bk2, bk3};

    if (t < 192) sp[t] = pc[b * 192 + t];
    __syncthreads();

    const float* WX = Ws[XI[p]]; const float* bX = bs[XI[p]];
    const float* WY = Ws[YI[p]]; const float* bY = bs[YI[p]];

    for (int idx = t; idx < NP * DD; idx += 256) {
        int n = idx >> 6, d = idx & 63;
        float x0 = sp[n * 3 + 0], x1 = sp[n * 3 + 1], x2 = sp[n * 3 + 2];
        sX[n][d] = bX[d] + x0 * WX[d] + x1 * WX[64 + d] + x2 * WX[128 + d];
        sY[n][d] = bY[d] + x0 * WY[d] + x1 * WY[64 + d] + x2 * WY[128 + d];
    }
    __syncthreads();

    for (int idx = t; idx < NP * NP; idx += 256) {
        int n = idx >> 6, m = idx & 63;
        float s = 0.f;
        #pragma unroll
        for (int d = 0; d < DD; d++)
            s = fmaf(sX[n][d], sY[m][d], s);
        g_E[p][b][idx] = s * 0.0625f;
    }
}

// ---------------------------------------------------------------------------
// Kernel C: grid=(i=64,b=32), 512 threads, occ-2 (8 warps/SMSP).
// Thread = (k = t&63, l-quad lq = u*8 + (t>>6)), 2 f16x2 streams per unit.
// SA folds E0+E1; SB folds E2; ec = E5[l][k]. Crosses scaled 1/8;
// 8-j f16 windows; x64 flush into f32x2 accumulators.
// ---------------------------------------------------------------------------
__global__ void __launch_bounds__(512, 2) kC(const float* __restrict__ pc,
                                             const float* __restrict__ W1,
                                             const float* __restrict__ b1,
                                             const float* __restrict__ W2,
                                             const float* __restrict__ b2,
                                             float* __restrict__ out)
{
    __shared__ __align__(16) __half2 SA2h[64 * 64];   // 16 KB  {a,a} per (j,k)
    __shared__ __align__(16) __half  SB4h[64 * 64];   // 8 KB   b per (j,l)
    __shared__ __align__(16) __half2 DJh[64][4];      // 2 KB   {x,x},{y,y},{z,z},pad
    __shared__ float4  dS[NP];                        // 1 KB
    __shared__ float   sS[6];
    __shared__ float   red[16];
    __shared__ float   sbat[BSZ];
    __shared__ int     sflag;

    int i = blockIdx.x, b = blockIdx.y, t = threadIdx.x;

    const float* E0r = &g_E[0][b][i * 64];
    const float* E1r = &g_E[1][b][i * 64];
    const float* E2r = &g_E[2][b][i * 64];
    const float* E3b = g_E[3][b];
    const float* E4b = g_E[4][b];

    for (int idx = t; idx < NP * NP; idx += 512) {
        int j = idx >> 6, c = idx & 63;
        float av = E3b[idx] + E0r[j] + E1r[c];       // E1 folded into SA
        SA2h[(j << 6) + c] = __float2half2_rn(av);
        float bv = E4b[idx] + E2r[c];
        SB4h[(j << 6) + c] = __float2half_rn(bv);
    }
    if (t < 64) {
        float ix = pc[b * 192 + i * 3 + 0];
        float iy = pc[b * 192 + i * 3 + 1];
        float iz = pc[b * 192 + i * 3 + 2];
        float dx = pc[b * 192 + t * 3 + 0] - ix;
        float dy = pc[b * 192 + t * 3 + 1] - iy;
        float dz = pc[b * 192 + t * 3 + 2] - iz;
        dS[t] = make_float4(dx, dy, dz, 0.f);
    }
    __syncthreads();
    if (t < 64) {
        float4 d = dS[t];
        DJh[t][0] = __float2half2_rn(d.x);
        DJh[t][1] = __float2half2_rn(d.y);
        DJh[t][2] = __float2half2_rn(d.z);
        DJh[t][3] = __float2half2_rn(0.f);
    } else if (t < 70) {
        int e = t - 64;
        int c1 = 0, c2 = 0;
        if (e == 1) { c1 = 1; c2 = 1; }
        if (e == 2) { c1 = 2; c2 = 2; }
        if (e == 3) { c1 = 0; c2 = 1; }
        if (e == 4) { c1 = 0; c2 = 2; }
        if (e == 5) { c1 = 1; c2 = 2; }
        float s = 0.f;
        for (int j = 0; j < 64; j++) {
            const float* dp = reinterpret_cast<const float*>(&dS[j]);
            s = fmaf(dp[c1], dp[c2], s);
        }
        sS[e] = s;
    }
    __syncthreads();

    const float* E5b = g_E[5][b];            // [l][k]
    int k = t & 63;

    float4 dk = dS[k];
    float Sxx = sS[0], Syy = sS[1], Szz = sS[2];
    float Sxy2 = 2.f * sS[3], Sxz2 = 2.f * sS[4], Syz2 = 2.f * sS[5];

    const __half2 hzero = __float2half2_rn(0.f);
    const ull C64 = pk2(64.f, 64.f);
    ull acc0 = pk2(0.f, 0.f), acc1 = acc0;
    float qsum = 0.f;

    #pragma unroll 1
    for (int u = 0; u < 2; u++) {
        int lq = u * 8 + (t >> 6);           // 0..15, warp-uniform
        int l0 = lq * 4;

        // 4 cross products + closed-form ungated half
        float cxs[4], cys[4], czs[4];
        #pragma unroll
        for (int m = 0; m < 4; m++) {
            float4 dl = dS[l0 + m];
            float cx = dk.y * dl.z - dk.z * dl.y;
            float cy = dk.z * dl.x - dk.x * dl.z;
            float cz = dk.x * dl.y - dk.y * dl.x;
            cxs[m] = cx; cys[m] = cy; czs[m] = cz;
            qsum += cx * (fmaf(Sxy2, cy, fmaf(Sxz2, cz, Sxx * cx)))
                  + cy * fmaf(Syz2, cz, Syy * cy) + cz * cz * Szz;
        }

        const float S8 = 0.125f;
        __half2 cx01 = __floats2half2_rn(cxs[0] * S8, cxs[1] * S8);
        __half2 cy01 = __floats2half2_rn(cys[0] * S8, cys[1] * S8);
        __half2 cz01 = __floats2half2_rn(czs[0] * S8, czs[1] * S8);
        __half2 cx23 = __floats2half2_rn(cxs[2] * S8, cxs[3] * S8);
        __half2 cy23 = __floats2half2_rn(cys[2] * S8, cys[3] * S8);
        __half2 cz23 = __floats2half2_rn(czs[2] * S8, czs[3] * S8);

        __half2 ec01 = __floats2half2_rn(E5b[(l0 + 0) * 64 + k], E5b[(l0 + 1) * 64 + k]);
        __half2 ec23 = __floats2half2_rn(E5b[(l0 + 2) * 64 + k], E5b[(l0 + 3) * 64 + k]);

        const __half* SBbase = SB4h + (lq << 2);
        __half2 win0 = hzero, win1 = hzero;

        #pragma unroll 8
        for (int j = 0; j < 64; j++) {
            __half2 aa = SA2h[(j << 6) + k];                                // LDS.32
            uint2 bqv = *reinterpret_cast<const uint2*>(SBbase + (j << 6)); // LDS.64 bcast
            uint4 djv = *reinterpret_cast<const uint4*>(&DJh[j][0]);        // LDS.128 bcast

            __half2 e0 = __hadd2(__hadd2(aa, u2h(bqv.x)), ec01);
            __half2 e1 = __hadd2(__hadd2(aa, u2h(bqv.y)), ec23);
            __half2 t0 = tanh2h(e0);
            __half2 t1 = tanh2h(e1);

            __half2 xx = u2h(djv.x), yy = u2h(djv.y), zz = u2h(djv.z);
            __half2 d0 = __hfma2(cx01, xx, __hfma2(cy01, yy, __hmul2(cz01, zz)));
            __half2 d1 = __hfma2(cx23, xx, __hfma2(cy23, yy, __hmul2(cz23, zz)));

            win0 = __hfma2(__hmul2(d0, d0), t0, win0);
            win1 = __hfma2(__hmul2(d1, d1), t1, win1);

            if ((j & 7) == 7) {   // flush windows (static under unroll 8)
                acc0 = fma2(pk2(__low2float(win0), __high2float(win0)), C64, acc0);
                acc1 = fma2(pk2(__low2float(win1), __high2float(win1)), C64, acc1);
                win0 = hzero; win1 = hzero;
            }
        }
    }

    float r0, r1, r2, r3;
    upk2(acc0, r0, r1); upk2(acc1, r2, r3);
    float v = ((r0 + r1) + (r2 + r3)) + qsum;
    #pragma unroll
    for (int off = 16; off > 0; off >>= 1)
        v += __shfl_xor_sync(0xFFFFFFFFu, v, off);
    if ((t & 31) == 0) red[t >> 5] = v;
    __syncthreads();
    if (t == 0) {
        float s = 0.f;
        #pragma unroll
        for (int w = 0; w < 16; w++) s += red[w];
        g_anchor[b * 64 + i] = s * 0.5f;
    }

    // ---- fused head: last finishing block reduces + runs the MLP ----
    if (t == 0) {
        __threadfence();
        unsigned vdone = atomicAdd(&g_done, 1u);
        sflag = (vdone == (unsigned)(NP * BSZ - 1));
    }
    __syncthreads();
    if (sflag) {
        if (t < 256) {
            int bb = t >> 3, p = t & 7;
            float s = 0.f;
            #pragma unroll
            for (int m = 0; m < 8; m++) s += g_anchor[bb * 64 + p + 8 * m];
            s += __shfl_xor_sync(0xFFFFFFFFu, s, 1);
            s += __shfl_xor_sync(0xFFFFFFFFu, s, 2);
            s += __shfl_xor_sync(0xFFFFFFFFu, s, 4);
            if (p == 0) sbat[bb] = s;
        }
        __syncthreads();
        if (t < 256) {
            int bb = t >> 3, p = t & 7;
            float sv = sbat[bb] * (1.0f / 16777216.0f);   // / N^3 / N
            float acc = 0.f;
            #pragma unroll
            for (int m = 0; m < 4; m++) {
                int j = p + 8 * m;
                float x = sv * W1[j] + b1[j];
                float uu = 0.7978845608028654f * (x + 0.044715f * x * x * x);
                float h = 0.5f * x * (1.0f + tanhf(uu));
                acc += h * W2[j];
            }
            acc += __shfl_xor_sync(0xFFFFFFFFu, acc, 1);
            acc += __shfl_xor_sync(0xFFFFFFFFu, acc, 2);
            acc += __shfl_xor_sync(0xFFFFFFFFu, acc, 4);
            if (p == 0) out[bb] = acc + b2[0];
        }
    }
}

// ---------------------------------------------------------------------------
extern "C" void kernel_launch(void* const* d_in, const int* in_sizes, int n_in,
                              void* d_out, int out_size)
{
    const float* pc  = (const float*)d_in[0];
    const float* Wq  = (const float*)d_in[1];
    const float* bq  = (const float*)d_in[2];
    const float* Wk1 = (const float*)d_in[3];
    const float* bk1 = (const float*)d_in[4];
    const float* Wk2 = (const float*)d_in[5];
    const float* bk2 = (const float*)d_in[6];
    const float* Wk3 = (const float*)d_in[7];
    const float* bk3 = (const float*)d_in[8];
    const float* W1  = (const float*)d_in[9];
    const float* b1  = (const float*)d_in[10];
    const float* W2  = (const float*)d_in[11];
    const float* b2  = (const float*)d_in[12];
    float* out = (float*)d_out;

    kAB<<<dim3(6, BSZ), 256>>>(pc, Wq, bq, Wk1, bk1, Wk2, bk2, Wk3, bk3);
    kC<<<dim3(NP, BSZ), 512>>>(pc, W1, b1, W2, b2, out);
}

// round 14
// speedup vs baseline: 1.1434x; 1.1434x over previous
#include <cuda_runtime.h>
#include <cuda_bf16.h>
#include <cuda_fp16.h>

// ---------------------------------------------------------------------------
// Simplex4Net: B=32, N=64, D=64
//   kAB: fused projections + six Gram matrices * 0.0625, grid (6,32,2)
//        (n-split halves for 2x parallelism on the latency-bound Gram).
//   kC:  grid (64,32) x 512 threads, occ-2 — EXACT Round-10 code (verified
//        144.6 us): thread = (k, l-quad), 2 units, all-f16 inner chain,
//        gate split (closed-form ungated half), fused MLP head.
// ---------------------------------------------------------------------------

#define BSZ 32
#define NP  64
#define DD  64

__device__ float g_E[6][BSZ][NP * NP];   // 0:(i,j) 1:(i,k) 2:(i,l) 3:(j,k) 4:(j,l) 5:(l,k)^T
__device__ float g_anchor[BSZ * NP];
__device__ unsigned g_done;

typedef unsigned long long ull;

__device__ __forceinline__ ull pk2(float lo, float hi) {
    ull r; asm("mov.b64 %0, {%1, %2};" : "=l"(r) : "f"(lo), "f"(hi)); return r;
}
__device__ __forceinline__ void upk2(ull v, float& lo, float& hi) {
    asm("mov.b64 {%0, %1}, %2;" : "=f"(lo), "=f"(hi) : "l"(v));
}
__device__ __forceinline__ ull fma2(ull a, ull b, ull c) {
    ull r; asm("fma.rn.f32x2 %0, %1, %2, %3;" : "=l"(r) : "l"(a), "l"(b), "l"(c)); return r;
}
__device__ __forceinline__ __half2 tanh2h(__half2 x) {
    unsigned xu = *reinterpret_cast<unsigned*>(&x);
    unsigned yu;
    asm("tanh.approx.f16x2 %0, %1;" : "=r"(yu) : "r"(xu));
    return *reinterpret_cast<__half2*>(&yu);
}
__device__ __forceinline__ __half2 u2h(unsigned u) {
    return *reinterpret_cast<__half2*>(&u);
}

// ---------------------------------------------------------------------------
// kAB: grid (6,32,2), 256 threads. Block (p,b,z) builds Gram rows
// n in [z*32, z*32+32) of matrix p for batch b (pre-scaled 0.0625).
// p=5 stored transposed [l][k] overall (rows here are l).
// ---------------------------------------------------------------------------
__global__ void kAB(const float* __restrict__ pc,
                    const float* __restrict__ Wq,  const float* __restrict__ bq,
                    const float* __restrict__ Wk1, const float* __restrict__ bk1,
                    const float* __restrict__ Wk2, const float* __restrict__ bk2,
                    const float* __restrict__ Wk3, const float* __restrict__ bk3)
{
    int p = blockIdx.x, b = blockIdx.y, z = blockIdx.z, t = threadIdx.x;
    if (p == 0 && b == 0 && z == 0 && t == 0) g_done = 0;

    __shared__ float sp[NP * 3];
    __shared__ float sX[32][65];     // rows n0..n0+31 of X-projection
    __shared__ float sY[NP][65];     // all rows of Y-projection

    const int XI[6] = {0, 0, 0, 1, 1, 3};
    const int YI[6] = {1, 2, 3, 2, 3, 2};
    const float* Ws[4] = {Wq, Wk1, Wk2, Wk3};
    const float* bs[4] = {bq, bk1, bk2, bk3};

    if (t < 192) sp[t] = pc[b * 192 + t];
    __syncthreads();

    const float* WX = Ws[XI[p]]; const float* bX = bs[XI[p]];
    const float* WY = Ws[YI[p]]; const float* bY = bs[YI[p]];
    int n0 = z * 32;

    for (int idx = t; idx < 32 * DD; idx += 256) {
        int n = idx >> 6, d = idx & 63;
        int ng = n0 + n;
        float x0 = sp[ng * 3 + 0], x1 = sp[ng * 3 + 1], x2 = sp[ng * 3 + 2];
        sX[n][d] = bX[d] + x0 * WX[d] + x1 * WX[64 + d] + x2 * WX[128 + d];
    }
    for (int idx = t; idx < NP * DD; idx += 256) {
        int n = idx >> 6, d = idx & 63;
        float x0 = sp[n * 3 + 0], x1 = sp[n * 3 + 1], x2 = sp[n * 3 + 2];
        sY[n][d] = bY[d] + x0 * WY[d] + x1 * WY[64 + d] + x2 * WY[128 + d];
    }
    __syncthreads();

    for (int idx = t; idx < 32 * NP; idx += 256) {
        int n = idx >> 6, m = idx & 63;
        float s = 0.f;
        #pragma unroll
        for (int d = 0; d < DD; d++)
            s = fmaf(sX[n][d], sY[m][d], s);
        g_E[p][b][((n0 + n) << 6) + m] = s * 0.0625f;
    }
}

// ---------------------------------------------------------------------------
// Kernel C: grid=(i=64,b=32), 512 threads, occ-2 (8 warps/SMSP).
// Thread = (k = t&63, l-quad lq = u*8 + (t>>6)), 2 f16x2 streams per unit.
// EXACT Round-10 structure (verified fastest): SA=E3+E0, ekA separate,
// ec = ekk + E5[l][k]. Crosses scaled 1/8; 8-j f16 window; x64 flush.
// ---------------------------------------------------------------------------
__global__ void __launch_bounds__(512, 2) kC(const float* __restrict__ pc,
                                             const float* __restrict__ W1,
                                             const float* __restrict__ b1,
                                             const float* __restrict__ W2,
                                             const float* __restrict__ b2,
                                             float* __restrict__ out)
{
    __shared__ __align__(16) __half2 SA2h[64 * 64];   // 16 KB  {a,a} per (j,k)
    __shared__ __align__(16) __half  SB4h[64 * 64];   // 8 KB   b per (j,l)
    __shared__ __align__(16) __half2 DJh[64][4];      // 2 KB   {x,x},{y,y},{z,z},pad
    __shared__ float4  dS[NP];                        // 1 KB
    __shared__ float   ekA[NP];
    __shared__ float   sS[6];
    __shared__ float   red[16];
    __shared__ float   sbat[BSZ];
    __shared__ int     sflag;

    int i = blockIdx.x, b = blockIdx.y, t = threadIdx.x;

    const float* E0r = &g_E[0][b][i * 64];
    const float* E2r = &g_E[2][b][i * 64];
    const float* E3b = g_E[3][b];
    const float* E4b = g_E[4][b];

    for (int idx = t; idx < NP * NP; idx += 512) {
        int j = idx >> 6, c = idx & 63;
        float av = E3b[idx] + E0r[j];
        SA2h[(j << 6) + c] = __float2half2_rn(av);
        float bv = E4b[idx] + E2r[c];
        SB4h[(j << 6) + c] = __float2half_rn(bv);
    }
    if (t < 64) {
        ekA[t] = g_E[1][b][i * 64 + t];
        float ix = pc[b * 192 + i * 3 + 0];
        float iy = pc[b * 192 + i * 3 + 1];
        float iz = pc[b * 192 + i * 3 + 2];
        float dx = pc[b * 192 + t * 3 + 0] - ix;
        float dy = pc[b * 192 + t * 3 + 1] - iy;
        float dz = pc[b * 192 + t * 3 + 2] - iz;
        dS[t] = make_float4(dx, dy, dz, 0.f);
    }
    __syncthreads();
    if (t < 64) {
        float4 d = dS[t];
        DJh[t][0] = __float2half2_rn(d.x);
        DJh[t][1] = __float2half2_rn(d.y);
        DJh[t][2] = __float2half2_rn(d.z);
        DJh[t][3] = __float2half2_rn(0.f);
    } else if (t < 70) {
        int e = t - 64;
        int c1 = 0, c2 = 0;
        if (e == 1) { c1 = 1; c2 = 1; }
        if (e == 2) { c1 = 2; c2 = 2; }
        if (e == 3) { c1 = 0; c2 = 1; }
        if (e == 4) { c1 = 0; c2 = 2; }
        if (e == 5) { c1 = 1; c2 = 2; }
        float s = 0.f;
        for (int j = 0; j < 64; j++) {
            const float* dp = reinterpret_cast<const float*>(&dS[j]);
            s = fmaf(dp[c1], dp[c2], s);
        }
        sS[e] = s;
    }
    __syncthreads();

    const float* E5b = g_E[5][b];            // [l][k]
    int k = t & 63;

    float4 dk = dS[k];
    float ekk = ekA[k];
    float Sxx = sS[0], Syy = sS[1], Szz = sS[2];
    float Sxy2 = 2.f * sS[3], Sxz2 = 2.f * sS[4], Syz2 = 2.f * sS[5];

    const __half2 hzero = __float2half2_rn(0.f);
    const ull C64 = pk2(64.f, 64.f);
    ull acc0 = pk2(0.f, 0.f), acc1 = acc0;
    float qsum = 0.f;

    #pragma unroll 1
    for (int u = 0; u < 2; u++) {
        int lq = u * 8 + (t >> 6);           // 0..15, warp-uniform
        int l0 = lq * 4;

        float4 dA = dS[l0 + 0];
        float4 dB = dS[l0 + 1];
        float4 dC = dS[l0 + 2];
        float4 dD = dS[l0 + 3];

        float cAx = dk.y * dA.z - dk.z * dA.y, cAy = dk.z * dA.x - dk.x * dA.z, cAz = dk.x * dA.y - dk.y * dA.x;
        float cBx = dk.y * dB.z - dk.z * dB.y, cBy = dk.z * dB.x - dk.x * dB.z, cBz = dk.x * dB.y - dk.y * dB.x;
        float cCx = dk.y * dC.z - dk.z * dC.y, cCy = dk.z * dC.x - dk.x * dC.z, cCz = dk.x * dC.y - dk.y * dC.x;
        float cDx = dk.y * dD.z - dk.z * dD.y, cDy = dk.z * dD.x - dk.x * dD.z, cDz = dk.x * dD.y - dk.y * dD.x;

        // closed-form ungated half (exact f32): c^T S c per l
        {
            float qA = cAx * (fmaf(Sxy2, cAy, fmaf(Sxz2, cAz, Sxx * cAx)))
                     + cAy * fmaf(Syz2, cAz, Syy * cAy) + cAz * cAz * Szz;
            float qB = cBx * (fmaf(Sxy2, cBy, fmaf(Sxz2, cBz, Sxx * cBx)))
                     + cBy * fmaf(Syz2, cBz, Syy * cBy) + cBz * cBz * Szz;
            float qC = cCx * (fmaf(Sxy2, cCy, fmaf(Sxz2, cCz, Sxx * cCx)))
                     + cCy * fmaf(Syz2, cCz, Syy * cCy) + cCz * cCz * Szz;
            float qD = cDx * (fmaf(Sxy2, cDy, fmaf(Sxz2, cDz, Sxx * cDx)))
                     + cDy * fmaf(Syz2, cDz, Syy * cDy) + cDz * cDz * Szz;
            qsum += (qA + qB) + (qC + qD);
        }

        // f16 cross products, scaled 1/8 (restored x64 at flush)
        const float S8 = 0.125f;
        __half2 cx01 = __floats2half2_rn(cAx * S8, cBx * S8);
        __half2 cy01 = __floats2half2_rn(cAy * S8, cBy * S8);
        __half2 cz01 = __floats2half2_rn(cAz * S8, cBz * S8);
        __half2 cx23 = __floats2half2_rn(cCx * S8, cDx * S8);
        __half2 cy23 = __floats2half2_rn(cCy * S8, cDy * S8);
        __half2 cz23 = __floats2half2_rn(cCz * S8, cDz * S8);

        __half2 ecAh = __floats2half2_rn(ekk + E5b[(l0 + 0) * 64 + k], ekk + E5b[(l0 + 1) * 64 + k]);
        __half2 ecBh = __floats2half2_rn(ekk + E5b[(l0 + 2) * 64 + k], ekk + E5b[(l0 + 3) * 64 + k]);

        const __half* SBbase = SB4h + (lq << 2);
        __half2 winP = hzero, winQ = hzero;

        #pragma unroll 8
        for (int j = 0; j < 64; j++) {
            __half2 aa = SA2h[(j << 6) + k];                                // LDS.32
            uint2 bqv = *reinterpret_cast<const uint2*>(SBbase + (j << 6)); // LDS.64 bcast
            uint4 djv = *reinterpret_cast<const uint4*>(&DJh[j][0]);        // LDS.128 bcast

            __half2 b01 = u2h(bqv.x), b23 = u2h(bqv.y);
            __half2 e01 = __hadd2(__hadd2(aa, b01), ecAh);
            __half2 e23 = __hadd2(__hadd2(aa, b23), ecBh);
            __half2 t01 = tanh2h(e01);
            __half2 t23 = tanh2h(e23);

            __half2 xx = u2h(djv.x), yy = u2h(djv.y), zz = u2h(djv.z);
            __half2 d01 = __hfma2(cx01, xx, __hfma2(cy01, yy, __hmul2(cz01, zz)));
            __half2 d23 = __hfma2(cx23, xx, __hfma2(cy23, yy, __hmul2(cz23, zz)));

            winP = __hfma2(__hmul2(d01, d01), t01, winP);
            winQ = __hfma2(__hmul2(d23, d23), t23, winQ);

            if ((j & 7) == 7) {   // flush window
                acc0 = fma2(pk2(__low2float(winP), __high2float(winP)), C64, acc0);
                acc1 = fma2(pk2(__low2float(winQ), __high2float(winQ)), C64, acc1);
                winP = hzero; winQ = hzero;
            }
        }
    }

    float r0, r1, r2, r3;
    upk2(acc0, r0, r1); upk2(acc1, r2, r3);
    float v = ((r0 + r1) + (r2 + r3)) + qsum;
    #pragma unroll
    for (int off = 16; off > 0; off >>= 1)
        v += __shfl_xor_sync(0xFFFFFFFFu, v, off);
    if ((t & 31) == 0) red[t >> 5] = v;
    __syncthreads();
    if (t == 0) {
        float s = 0.f;
        #pragma unroll
        for (int w = 0; w < 16; w++) s += red[w];
        g_anchor[b * 64 + i] = s * 0.5f;
    }

    // ---- fused head: last finishing block reduces + runs the MLP ----
    if (t == 0) {
        __threadfence();
        unsigned vdone = atomicAdd(&g_done, 1u);
        sflag = (vdone == (unsigned)(NP * BSZ - 1));
    }
    __syncthreads();
    if (sflag) {
        if (t < 256) {
            int bb = t >> 3, p = t & 7;
            float s = 0.f;
            #pragma unroll
            for (int m = 0; m < 8; m++) s += g_anchor[bb * 64 + p + 8 * m];
            s += __shfl_xor_sync(0xFFFFFFFFu, s, 1);
            s += __shfl_xor_sync(0xFFFFFFFFu, s, 2);
            s += __shfl_xor_sync(0xFFFFFFFFu, s, 4);
            if (p == 0) sbat[bb] = s;
        }
        __syncthreads();
        if (t < 256) {
            int bb = t >> 3, p = t & 7;
            float sv = sbat[bb] * (1.0f / 16777216.0f);   // / N^3 / N
            float acc = 0.f;
            #pragma unroll
            for (int m = 0; m < 4; m++) {
                int j = p + 8 * m;
                float x = sv * W1[j] + b1[j];
                float uu = 0.7978845608028654f * (x + 0.044715f * x * x * x);
                float h = 0.5f * x * (1.0f + tanhf(uu));
                acc += h * W2[j];
            }
            acc += __shfl_xor_sync(0xFFFFFFFFu, acc, 1);
            acc += __shfl_xor_sync(0xFFFFFFFFu, acc, 2);
            acc += __shfl_xor_sync(0xFFFFFFFFu, acc, 4);
            if (p == 0) out[bb] = acc + b2[0];
        }
    }
}

// ---------------------------------------------------------------------------
extern "C" void kernel_launch(void* const* d_in, const int* in_sizes, int n_in,
                              void* d_out, int out_size)
{
    const float* pc  = (const float*)d_in[0];
    const float* Wq  = (const float*)d_in[1];
    const float* bq  = (const float*)d_in[2];
    const float* Wk1 = (const float*)d_in[3];
    const float* bk1 = (const float*)d_in[4];
    const float* Wk2 = (const float*)d_in[5];
    const float* bk2 = (const float*)d_in[6];
    const float* Wk3 = (const float*)d_in[7];
    const float* bk3 = (const float*)d_in[8];
    const float* W1  = (const float*)d_in[9];
    const float* b1  = (const float*)d_in[10];
    const float* W2  = (const float*)d_in[11];
    const float* b2  = (const float*)d_in[12];
    float* out = (float*)d_out;

    kAB<<<dim3(6, BSZ, 2), 256>>>(pc, Wq, bq, Wk1, bk1, Wk2, bk2, Wk3, bk3);
    kC<<<dim3(NP, BSZ), 512>>>(pc, W1, b1, W2, b2, out);
}

// round 15
// speedup vs baseline: 1.1572x; 1.0120x over previous
#include <cuda_runtime.h>
#include <cuda_bf16.h>
#include <cuda_fp16.h>

// ---------------------------------------------------------------------------
// Simplex4Net: B=32, N=64, D=64
//   kAB: fused projections + six Gram matrices * 0.0625 -> __half g_Eh,
//        grid (6,32,2) (n-split halves).
//   kC:  grid (64,32) x 512 threads, occ-2. Inner loop byte-identical to the
//        verified 144.6us Round-10 schedule; build path reworked to packed
//        f16 loads (half the instructions, half the traffic).
// ---------------------------------------------------------------------------

#define BSZ 32
#define NP  64
#define DD  64

__device__ __half g_Eh[6][BSZ][NP * NP];  // 0:(i,j) 1:(i,k) 2:(i,l) 3:(j,k) 4:(j,l) 5:(l,k)^T
__device__ float  g_anchor[BSZ * NP];
__device__ unsigned g_done;

typedef unsigned long long ull;

__device__ __forceinline__ ull pk2(float lo, float hi) {
    ull r; asm("mov.b64 %0, {%1, %2};" : "=l"(r) : "f"(lo), "f"(hi)); return r;
}
__device__ __forceinline__ void upk2(ull v, float& lo, float& hi) {
    asm("mov.b64 {%0, %1}, %2;" : "=f"(lo), "=f"(hi) : "l"(v));
}
__device__ __forceinline__ ull fma2(ull a, ull b, ull c) {
    ull r; asm("fma.rn.f32x2 %0, %1, %2, %3;" : "=l"(r) : "l"(a), "l"(b), "l"(c)); return r;
}
__device__ __forceinline__ __half2 tanh2h(__half2 x) {
    unsigned xu = *reinterpret_cast<unsigned*>(&x);
    unsigned yu;
    asm("tanh.approx.f16x2 %0, %1;" : "=r"(yu) : "r"(xu));
    return *reinterpret_cast<__half2*>(&yu);
}
__device__ __forceinline__ __half2 u2h(unsigned u) {
    return *reinterpret_cast<__half2*>(&u);
}

// ---------------------------------------------------------------------------
// kAB: grid (6,32,2), 256 threads. Block (p,b,z) builds Gram rows
// n in [z*32, z*32+32) of matrix p for batch b (pre-scaled 0.0625), f16 out.
// p=5 stored transposed [l][k] overall (rows here are l).
// ---------------------------------------------------------------------------
__global__ void kAB(const float* __restrict__ pc,
                    const float* __restrict__ Wq,  const float* __restrict__ bq,
                    const float* __restrict__ Wk1, const float* __restrict__ bk1,
                    const float* __restrict__ Wk2, const float* __restrict__ bk2,
                    const float* __restrict__ Wk3, const float* __restrict__ bk3)
{
    int p = blockIdx.x, b = blockIdx.y, z = blockIdx.z, t = threadIdx.x;
    if (p == 0 && b == 0 && z == 0 && t == 0) g_done = 0;

    __shared__ float sp[NP * 3];
    __shared__ float sX[32][65];
    __shared__ float sY[NP][65];

    const int XI[6] = {0, 0, 0, 1, 1, 3};
    const int YI[6] = {1, 2, 3, 2, 3, 2};
    const float* Ws[4] = {Wq, Wk1, Wk2, Wk3};
    const float* bs[4] = {bq, bk1, bk2, bk3};

    if (t < 192) sp[t] = pc[b * 192 + t];
    __syncthreads();

    const float* WX = Ws[XI[p]]; const float* bX = bs[XI[p]];
    const float* WY = Ws[YI[p]]; const float* bY = bs[YI[p]];
    int n0 = z * 32;

    for (int idx = t; idx < 32 * DD; idx += 256) {
        int n = idx >> 6, d = idx & 63;
        int ng = n0 + n;
        float x0 = sp[ng * 3 + 0], x1 = sp[ng * 3 + 1], x2 = sp[ng * 3 + 2];
        sX[n][d] = bX[d] + x0 * WX[d] + x1 * WX[64 + d] + x2 * WX[128 + d];
    }
    for (int idx = t; idx < NP * DD; idx += 256) {
        int n = idx >> 6, d = idx & 63;
        float x0 = sp[n * 3 + 0], x1 = sp[n * 3 + 1], x2 = sp[n * 3 + 2];
        sY[n][d] = bY[d] + x0 * WY[d] + x1 * WY[64 + d] + x2 * WY[128 + d];
    }
    __syncthreads();

    for (int idx = t; idx < 32 * NP; idx += 256) {
        int n = idx >> 6, m = idx & 63;
        float s = 0.f;
        #pragma unroll
        for (int d = 0; d < DD; d++)
            s = fmaf(sX[n][d], sY[m][d], s);
        g_Eh[p][b][((n0 + n) << 6) + m] = __float2half_rn(s * 0.0625f);
    }
}

// ---------------------------------------------------------------------------
// Kernel C: grid=(i=64,b=32), 512 threads, occ-2 (8 warps/SMSP).
// Thread = (k = t&63, l-quad lq = u*8 + (t>>6)), 2 f16x2 streams per unit.
// Inner loop identical to the verified Round-10 schedule. Build path uses
// packed f16 loads from g_Eh.
// ---------------------------------------------------------------------------
__global__ void __launch_bounds__(512, 2) kC(const float* __restrict__ pc,
                                             const float* __restrict__ W1,
                                             const float* __restrict__ b1,
                                             const float* __restrict__ W2,
                                             const float* __restrict__ b2,
                                             float* __restrict__ out)
{
    __shared__ __align__(16) __half2 SA2h[64 * 64];   // 16 KB  {a,a} per (j,k)
    __shared__ __align__(16) __half  SB4h[64 * 64];   // 8 KB   b per (j,l)
    __shared__ __align__(16) __half2 DJh[64][4];      // 2 KB   {x,x},{y,y},{z,z},pad
    __shared__ float4  dS[NP];                        // 1 KB
    __shared__ __half  ekAh[NP];
    __shared__ float   sS[6];
    __shared__ float   red[16];
    __shared__ float   sbat[BSZ];
    __shared__ int     sflag;

    int i = blockIdx.x, b = blockIdx.y, t = threadIdx.x;

    const __half2* E3p = reinterpret_cast<const __half2*>(g_Eh[3][b]);
    const __half2* E4p = reinterpret_cast<const __half2*>(g_Eh[4][b]);
    const __half2* E2p = reinterpret_cast<const __half2*>(g_Eh[2][b]) + i * 32;
    const __half*  E0p = g_Eh[0][b] + i * 64;
    __half2* SBh2 = reinterpret_cast<__half2*>(SB4h);

    // build: 2048 half2-pairs cover both SA (with {a,a} replication) and SB
    for (int idx = t; idx < 2048; idx += 512) {
        int j = idx >> 5, cp = idx & 31;
        __half2 av2 = __hadd2(E3p[(j << 5) + cp], __half2half2(E0p[j]));
        __half2 lo = __lows2half2(av2, av2);
        __half2 hi = __highs2half2(av2, av2);
        uint2 pr;
        pr.x = *reinterpret_cast<unsigned*>(&lo);
        pr.y = *reinterpret_cast<unsigned*>(&hi);
        *reinterpret_cast<uint2*>(&SA2h[(j << 6) + (cp << 1)]) = pr;
        SBh2[(j << 5) + cp] = __hadd2(E4p[(j << 5) + cp], E2p[cp]);
    }
    if (t < 64) {
        ekAh[t] = g_Eh[1][b][i * 64 + t];
        float ix = pc[b * 192 + i * 3 + 0];
        float iy = pc[b * 192 + i * 3 + 1];
        float iz = pc[b * 192 + i * 3 + 2];
        float dx = pc[b * 192 + t * 3 + 0] - ix;
        float dy = pc[b * 192 + t * 3 + 1] - iy;
        float dz = pc[b * 192 + t * 3 + 2] - iz;
        dS[t] = make_float4(dx, dy, dz, 0.f);
    }
    __syncthreads();
    if (t < 64) {
        float4 d = dS[t];
        DJh[t][0] = __float2half2_rn(d.x);
        DJh[t][1] = __float2half2_rn(d.y);
        DJh[t][2] = __float2half2_rn(d.z);
        DJh[t][3] = __float2half2_rn(0.f);
    } else if (t < 70) {
        int e = t - 64;
        int c1 = 0, c2 = 0;
        if (e == 1) { c1 = 1; c2 = 1; }
        if (e == 2) { c1 = 2; c2 = 2; }
        if (e == 3) { c1 = 0; c2 = 1; }
        if (e == 4) { c1 = 0; c2 = 2; }
        if (e == 5) { c1 = 1; c2 = 2; }
        float s = 0.f;
        for (int j = 0; j < 64; j++) {
            const float* dp = reinterpret_cast<const float*>(&dS[j]);
            s = fmaf(dp[c1], dp[c2], s);
        }
        sS[e] = s;
    }
    __syncthreads();

    const __half* E5p = g_Eh[5][b];          // [l][k]
    int k = t & 63;

    float4 dk = dS[k];
    __half2 ekk2 = __half2half2(ekAh[k]);
    float Sxx = sS[0], Syy = sS[1], Szz = sS[2];
    float Sxy2 = 2.f * sS[3], Sxz2 = 2.f * sS[4], Syz2 = 2.f * sS[5];

    const __half2 hzero = __float2half2_rn(0.f);
    const ull C64 = pk2(64.f, 64.f);
    ull acc0 = pk2(0.f, 0.f), acc1 = acc0;
    float qsum = 0.f;

    #pragma unroll 1
    for (int u = 0; u < 2; u++) {
        int lq = u * 8 + (t >> 6);           // 0..15, warp-uniform
        int l0 = lq * 4;

        float4 dA = dS[l0 + 0];
        float4 dB = dS[l0 + 1];
        float4 dC = dS[l0 + 2];
        float4 dD = dS[l0 + 3];

        float cAx = dk.y * dA.z - dk.z * dA.y, cAy = dk.z * dA.x - dk.x * dA.z, cAz = dk.x * dA.y - dk.y * dA.x;
        float cBx = dk.y * dB.z - dk.z * dB.y, cBy = dk.z * dB.x - dk.x * dB.z, cBz = dk.x * dB.y - dk.y * dB.x;
        float cCx = dk.y * dC.z - dk.z * dC.y, cCy = dk.z * dC.x - dk.x * dC.z, cCz = dk.x * dC.y - dk.y * dC.x;
        float cDx = dk.y * dD.z - dk.z * dD.y, cDy = dk.z * dD.x - dk.x * dD.z, cDz = dk.x * dD.y - dk.y * dD.x;

        // closed-form ungated half (exact f32): c^T S c per l
        {
            float qA = cAx * (fmaf(Sxy2, cAy, fmaf(Sxz2, cAz, Sxx * cAx)))
                     + cAy * fmaf(Syz2, cAz, Syy * cAy) + cAz * cAz * Szz;
            float qB = cBx * (fmaf(Sxy2, cBy, fmaf(Sxz2, cBz, Sxx * cBx)))
                     + cBy * fmaf(Syz2, cBz, Syy * cBy) + cBz * cBz * Szz;
            float qC = cCx * (fmaf(Sxy2, cCy, fmaf(Sxz2, cCz, Sxx * cCx)))
                     + cCy * fmaf(Syz2, cCz, Syy * cCy) + cCz * cCz * Szz;
            float qD = cDx * (fmaf(Sxy2, cDy, fmaf(Sxz2, cDz, Sxx * cDx)))
                     + cDy * fmaf(Syz2, cDz, Syy * cDy) + cDz * cDz * Szz;
            qsum += (qA + qB) + (qC + qD);
        }

        // f16 cross products, scaled 1/8 (restored x64 at flush)
        const float S8 = 0.125f;
        __half2 cx01 = __floats2half2_rn(cAx * S8, cBx * S8);
        __half2 cy01 = __floats2half2_rn(cAy * S8, cBy * S8);
        __half2 cz01 = __floats2half2_rn(cAz * S8, cBz * S8);
        __half2 cx23 = __floats2half2_rn(cCx * S8, cDx * S8);
        __half2 cy23 = __floats2half2_rn(cCy * S8, cDy * S8);
        __half2 cz23 = __floats2half2_rn(cCz * S8, cDz * S8);

        __half2 ecAh = __hadd2(ekk2, __halves2half2(E5p[(l0 + 0) * 64 + k], E5p[(l0 + 1) * 64 + k]));
        __half2 ecBh = __hadd2(ekk2, __halves2half2(E5p[(l0 + 2) * 64 + k], E5p[(l0 + 3) * 64 + k]));

        const __half* SBbase = SB4h + (lq << 2);
        __half2 winP = hzero, winQ = hzero;

        #pragma unroll 8
        for (int j = 0; j < 64; j++) {
            __half2 aa = SA2h[(j << 6) + k];                                // LDS.32
            uint2 bqv = *reinterpret_cast<const uint2*>(SBbase + (j << 6)); // LDS.64 bcast
            uint4 djv = *reinterpret_cast<const uint4*>(&DJh[j][0]);        // LDS.128 bcast

            __half2 b01 = u2h(bqv.x), b23 = u2h(bqv.y);
            __half2 e01 = __hadd2(__hadd2(aa, b01), ecAh);
            __half2 e23 = __hadd2(__hadd2(aa, b23), ecBh);
            __half2 t01 = tanh2h(e01);
            __half2 t23 = tanh2h(e23);

            __half2 xx = u2h(djv.x), yy = u2h(djv.y), zz = u2h(djv.z);
            __half2 d01 = __hfma2(cx01, xx, __hfma2(cy01, yy, __hmul2(cz01, zz)));
            __half2 d23 = __hfma2(cx23, xx, __hfma2(cy23, yy, __hmul2(cz23, zz)));

            winP = __hfma2(__hmul2(d01, d01), t01, winP);
            winQ = __hfma2(__hmul2(d23, d23), t23, winQ);

            if ((j & 7) == 7) {   // flush window
                acc0 = fma2(pk2(__low2float(winP), __high2float(winP)), C64, acc0);
                acc1 = fma2(pk2(__low2float(winQ), __high2float(winQ)), C64, acc1);
                winP = hzero; winQ = hzero;
            }
        }
    }

    float r0, r1, r2, r3;
    upk2(acc0, r0, r1); upk2(acc1, r2, r3);
    float v = ((r0 + r1) + (r2 + r3)) + qsum;
    #pragma unroll
    for (int off = 16; off > 0; off >>= 1)
        v += __shfl_xor_sync(0xFFFFFFFFu, v, off);
    if ((t & 31) == 0) red[t >> 5] = v;
    __syncthreads();
    if (t == 0) {
        float s = 0.f;
        #pragma unroll
        for (int w = 0; w < 16; w++) s += red[w];
        g_anchor[b * 64 + i] = s * 0.5f;
    }

    // ---- fused head: last finishing block reduces + runs the MLP ----
    if (t == 0) {
        __threadfence();
        unsigned vdone = atomicAdd(&g_done, 1u);
        sflag = (vdone == (unsigned)(NP * BSZ - 1));
    }
    __syncthreads();
    if (sflag) {
        if (t < 256) {
            int bb = t >> 3, p = t & 7;
            float s = 0.f;
            #pragma unroll
            for (int m = 0; m < 8; m++) s += g_anchor[bb * 64 + p + 8 * m];
            s += __shfl_xor_sync(0xFFFFFFFFu, s, 1);
            s += __shfl_xor_sync(0xFFFFFFFFu, s, 2);
            s += __shfl_xor_sync(0xFFFFFFFFu, s, 4);
            if (p == 0) sbat[bb] = s;
        }
        __syncthreads();
        if (t < 256) {
            int bb = t >> 3, p = t & 7;
            float sv = sbat[bb] * (1.0f / 16777216.0f);   // / N^3 / N
            float acc = 0.f;
            #pragma unroll
            for (int m = 0; m < 4; m++) {
                int j = p + 8 * m;
                float x = sv * W1[j] + b1[j];
                float uu = 0.7978845608028654f * (x + 0.044715f * x * x * x);
                float h = 0.5f * x * (1.0f + tanhf(uu));
                acc += h * W2[j];
            }
            acc += __shfl_xor_sync(0xFFFFFFFFu, acc, 1);
            acc += __shfl_xor_sync(0xFFFFFFFFu, acc, 2);
            acc += __shfl_xor_sync(0xFFFFFFFFu, acc, 4);
            if (p == 0) out[bb] = acc + b2[0];
        }
    }
}

// ---------------------------------------------------------------------------
extern "C" void kernel_launch(void* const* d_in, const int* in_sizes, int n_in,
                              void* d_out, int out_size)
{
    const float* pc  = (const float*)d_in[0];
    const float* Wq  = (const float*)d_in[1];
    const float* bq  = (const float*)d_in[2];
    const float* Wk1 = (const float*)d_in[3];
    const float* bk1 = (const float*)d_in[4];
    const float* Wk2 = (const float*)d_in[5];
    const float* bk2 = (const float*)d_in[6];
    const float* Wk3 = (const float*)d_in[7];
    const float* bk3 = (const float*)d_in[8];
    const float* W1  = (const float*)d_in[9];
    const float* b1  = (const float*)d_in[10];
    const float* W2  = (const float*)d_in[11];
    const float* b2  = (const float*)d_in[12];
    float* out = (float*)d_out;

    kAB<<<dim3(6, BSZ, 2), 256>>>(pc, Wq, bq, Wk1, bk1, Wk2, bk2, Wk3, bk3);
    kC<<<dim3(NP, BSZ), 512>>>(pc, W1, b1, W2, b2, out);
}